// round 17
// baseline (speedup 1.0000x reference)
#include <cuda_runtime.h>
#include <cuda_fp16.h>
#include <cstdint>

// Problem constants (fixed shapes for this dataset)
#define BB   4
#define NN   50000
#define CIN  64
#define EE   800000
#define HALF 32
#define BN   (BB * NN)           // 200000

#define HIST_BLOCKS  782         // ceil(EE/4 / 256), 4 edges/thread
#define SCANB_BLOCKS 49          // ceil(NN/1024), 1024 nodes/block (256 thr x 4)
#define PROJ_BLOCKS  1563        // ceil(NN / 32)
#define SCAT_BLOCKS  391         // ceil(EE/8 / 256), 8 edges/thread

// fused K1 block ranges (dispatch order = dependency-safe order)
#define SCANB_BASE   HIST_BLOCKS                         // 782
#define PROJ_BASE    (SCANB_BASE + SCANB_BLOCKS)         // 831
#define SCAT_BASE    (PROJ_BASE + PROJ_BLOCKS)           // 2394
#define K1_GRID      (SCAT_BASE + SCAT_BLOCKS)           // 2785

#define GATHER_TPB   64
#define GATHER_BLOCKS (NN / 2)   // 25000 blocks, 1 warp per node

// ---------------- scratch (device globals; zero-initialized at load) --------
__device__ __half g_hlin[NN * 128];    // [n][ch][b]  half, 12.8 MB (L2-resident)
__device__ int    g_counts[NN];        // kept zero between calls (scanB re-zeros)
__device__ int    g_offsets[NN + 1];
__device__ int    g_rank[EE];          // within-node rank of each edge
__device__ int2   g_csr[EE];           // .x = col, .y = bits(val)
__device__ int    g_blocksums[64];     // kept zero between calls (scatter re-zeros)
__device__ int    g_hist_done;         // phase flags; reset by gather each call
__device__ int    g_scan_done;

// ---------------- mma helper -------------------------------------------------
__device__ __forceinline__ void mma16816(float& d0, float& d1, float& d2, float& d3,
                                         unsigned a0, unsigned a1, unsigned a2, unsigned a3,
                                         unsigned b0, unsigned b1) {
    asm("mma.sync.aligned.m16n8k16.row.col.f32.f16.f16.f32 "
        "{%0,%1,%2,%3}, {%4,%5,%6,%7}, {%8,%9}, {%0,%1,%2,%3};"
        : "+f"(d0), "+f"(d1), "+f"(d2), "+f"(d3)
        : "r"(a0), "r"(a1), "r"(a2), "r"(a3), "r"(b0), "r"(b1));
}

// ---------------- phase-fence helpers ----------------------------------------
__device__ __forceinline__ void phase_signal(int* flag) {
    // all threads: order my global writes; then one arrival
    __threadfence();
    __syncthreads();
    if (threadIdx.x == 0) atomicAdd(flag, 1);
}
__device__ __forceinline__ void phase_wait(int* flag, int target) {
    if (threadIdx.x == 0) {
        while (atomicAdd(flag, 0) < target) __nanosleep(64);
    }
    __syncthreads();
    __threadfence();
}

// ---------------- K1: hist + scanB + HMMA proj + scatter (flag-chained) ------
#define XS_STRIDE 72    // halves; frag LDS bank = 4g+tig, conflict-free
#define SL_STRIDE 132   // halves per node in slin
#define SE_STRIDE 34    // floats per row in seye
#define SMEM_BYTES 28672

__global__ __launch_bounds__(256, 3) void k1_fused_kernel(
    const int*   __restrict__ rows,
    const int*   __restrict__ cols,
    const float* __restrict__ vals,
    const float* __restrict__ x,
    const float* __restrict__ Wlin,
    const float* __restrict__ Weye,
    const float* __restrict__ beye,
    float*       __restrict__ out)
{
    __shared__ __align__(16) char sm[SMEM_BYTES];
    const int tid = threadIdx.x;
    const int bid = blockIdx.x;

    if (bid < HIST_BLOCKS) {
        // ================= phase 1: histogram + rank + chunk sums ============
        int* sh = (int*)sm;
        if (tid < SCANB_BLOCKS) sh[tid] = 0;
        __syncthreads();

        int i = bid * 256 + tid;
        if (i < EE / 4) {
            int4 r = ((const int4*)rows)[i];
            int4 rk;
            rk.x = atomicAdd(&g_counts[r.x], 1); atomicAdd(&sh[r.x >> 10], 1);
            rk.y = atomicAdd(&g_counts[r.y], 1); atomicAdd(&sh[r.y >> 10], 1);
            rk.z = atomicAdd(&g_counts[r.z], 1); atomicAdd(&sh[r.z >> 10], 1);
            rk.w = atomicAdd(&g_counts[r.w], 1); atomicAdd(&sh[r.w >> 10], 1);
            ((int4*)g_rank)[i] = rk;
        }
        __syncthreads();
        if (tid < SCANB_BLOCKS && sh[tid]) atomicAdd(&g_blocksums[tid], sh[tid]);
        phase_signal(&g_hist_done);
        return;
    }

    if (bid < PROJ_BASE) {
        // ================= phase 2: scanB (256 thr, 4 nodes/thread) ==========
        const int j = bid - SCANB_BASE;        // 0..48
        phase_wait(&g_hist_done, HIST_BLOCKS);

        int* wsum = (int*)sm;                  // [8]
        int* sbase = (int*)sm + 8;
        const int lane = tid & 31, wid = tid >> 5;

        if (wid == 0) {
            int v = 0;
            for (int k = lane; k < j; k += 32) v += g_blocksums[k];
            #pragma unroll
            for (int d = 16; d > 0; d >>= 1) v += __shfl_down_sync(0xFFFFFFFFu, v, d);
            if (lane == 0) *sbase = v;
        }

        int i0 = j * 1024 + tid * 4;
        int c0 = 0, c1 = 0, c2 = 0, c3 = 0;
        bool full = (i0 + 3 < NN);
        if (full) {
            int4 c = *(const int4*)&g_counts[i0];
            c0 = c.x; c1 = c.y; c2 = c.z; c3 = c.w;
        } else {
            if (i0     < NN) c0 = g_counts[i0];
            if (i0 + 1 < NN) c1 = g_counts[i0 + 1];
            if (i0 + 2 < NN) c2 = g_counts[i0 + 2];
            if (i0 + 3 < NN) c3 = g_counts[i0 + 3];
        }
        int tsum = c0 + c1 + c2 + c3;

        // inclusive warp scan of tsum
        int xinc = tsum;
        #pragma unroll
        for (int d = 1; d < 32; d <<= 1) {
            int y = __shfl_up_sync(0xFFFFFFFFu, xinc, d);
            if (lane >= d) xinc += y;
        }
        if (lane == 31) wsum[wid] = xinc;
        __syncthreads();
        int wpre = 0;
        #pragma unroll
        for (int k = 0; k < 8; ++k) if (k < wid) wpre += wsum[k];
        int excl = (xinc - tsum) + wpre + *sbase;

        if (full) {
            int4 o;
            o.x = excl;
            o.y = excl + c0;
            o.z = excl + c0 + c1;
            o.w = excl + c0 + c1 + c2;
            *(int4*)&g_offsets[i0] = o;
            *(int4*)&g_counts[i0]  = make_int4(0, 0, 0, 0);
        } else {
            int run = excl;
            if (i0     < NN) { g_offsets[i0]     = run; g_counts[i0]     = 0; run += c0; }
            if (i0 + 1 < NN) { g_offsets[i0 + 1] = run; g_counts[i0 + 1] = 0; run += c1; }
            if (i0 + 2 < NN) { g_offsets[i0 + 2] = run; g_counts[i0 + 2] = 0; run += c2; }
            if (i0 + 3 < NN) { g_offsets[i0 + 3] = run; g_counts[i0 + 3] = 0; }
        }
        if (j == 0 && tid == 0) g_offsets[NN] = EE;
        phase_signal(&g_scan_done);
        return;
    }

    if (bid >= SCAT_BASE) {
        // ================= phase 4: atomic-free scatter (MLP 8) ==============
        const int sb = bid - SCAT_BASE;
        int i0 = sb * 512 + tid;
        int i1 = i0 + 256;
        bool v0ok = (i0 < EE / 4);
        bool v1ok = (i1 < EE / 4);

        // prefetch pure inputs while (possibly) waiting
        int4 ra, ca; float4 va;
        int4 rb, cb; float4 vb;
        if (v0ok) {
            ra = ((const int4*)rows)[i0];
            ca = __ldcs(((const int4*)cols) + i0);
            va = __ldcs(((const float4*)vals) + i0);
        }
        if (v1ok) {
            rb = ((const int4*)rows)[i1];
            cb = __ldcs(((const int4*)cols) + i1);
            vb = __ldcs(((const float4*)vals) + i1);
        }

        phase_wait(&g_scan_done, SCANB_BLOCKS);

        // scanB done reading g_blocksums: reset for the next invocation
        if (sb == 0 && tid < SCANB_BLOCKS) g_blocksums[tid] = 0;

        int4 ka, kb;
        if (v0ok) ka = __ldcs(((const int4*)g_rank) + i0);
        if (v1ok) kb = __ldcs(((const int4*)g_rank) + i1);

        if (v0ok) {
            int p0 = g_offsets[ra.x] + ka.x;
            int p1 = g_offsets[ra.y] + ka.y;
            int p2 = g_offsets[ra.z] + ka.z;
            int p3 = g_offsets[ra.w] + ka.w;
            g_csr[p0] = make_int2(ca.x, __float_as_int(va.x));
            g_csr[p1] = make_int2(ca.y, __float_as_int(va.y));
            g_csr[p2] = make_int2(ca.z, __float_as_int(va.z));
            g_csr[p3] = make_int2(ca.w, __float_as_int(va.w));
        }
        if (v1ok) {
            int p0 = g_offsets[rb.x] + kb.x;
            int p1 = g_offsets[rb.y] + kb.y;
            int p2 = g_offsets[rb.z] + kb.z;
            int p3 = g_offsets[rb.w] + kb.w;
            g_csr[p0] = make_int2(cb.x, __float_as_int(vb.x));
            g_csr[p1] = make_int2(cb.y, __float_as_int(vb.y));
            g_csr[p2] = make_int2(cb.z, __float_as_int(vb.z));
            g_csr[p3] = make_int2(cb.w, __float_as_int(vb.w));
        }
        return;
    }

    // ================= phase 3: HMMA projection ==============================
    __half* xs = (__half*)sm;                          // [128][XS_STRIDE]
    __half* wt = (__half*)(sm + 128 * XS_STRIDE * 2);  // [64][XS_STRIDE]

    const int node0 = (bid - PROJ_BASE) * 32;

    #pragma unroll
    for (int it = 0; it < 12; ++it) {
        int idx = tid + it * 256;                   // 0..3071
        if (idx < 2048) {
            int row = idx >> 4;                     // 0..127
            int c4  = (idx & 15) << 2;
            int b   = row >> 5;
            int node = row & 31;
            int nn  = node0 + node; if (nn >= NN) nn = NN - 1;
            float4 v = __ldcs((const float4*)(x + ((size_t)(b * NN + nn)) * 64 + c4));
            *(__half2*)&xs[row * XS_STRIDE + c4]     = __floats2half2_rn(v.x, v.y);
            *(__half2*)&xs[row * XS_STRIDE + c4 + 2] = __floats2half2_rn(v.z, v.w);
        } else {
            int id2 = idx - 2048;                   // 0..1023
            int row = id2 >> 4;                     // 0..63
            int c4  = (id2 & 15) << 2;
            const float* wsrc = (row < 32) ? (Wlin + row * 64 + c4)
                                           : (Weye + (row - 32) * 64 + c4);
            float4 w = *(const float4*)wsrc;
            *(__half2*)&wt[row * XS_STRIDE + c4]     = __floats2half2_rn(w.x, w.y);
            *(__half2*)&wt[row * XS_STRIDE + c4 + 2] = __floats2half2_rn(w.z, w.w);
        }
    }
    __syncthreads();

    const int warp = tid >> 5;
    const int lane = tid & 31;
    const int g    = lane >> 2;        // 0..7
    const int tig  = lane & 3;         // 0..3
    const int wrow = warp * 16;        // warp's A-row base

    float d[8][4];
    #pragma unroll
    for (int nf = 0; nf < 8; ++nf)
        #pragma unroll
        for (int k = 0; k < 4; ++k) d[nf][k] = 0.f;

    #pragma unroll
    for (int kc = 0; kc < 4; ++kc) {
        const int kb = kc * 16;
        unsigned a0 = *(const unsigned*)&xs[(wrow + g)     * XS_STRIDE + kb + 2 * tig];
        unsigned a1 = *(const unsigned*)&xs[(wrow + g + 8) * XS_STRIDE + kb + 2 * tig];
        unsigned a2 = *(const unsigned*)&xs[(wrow + g)     * XS_STRIDE + kb + 2 * tig + 8];
        unsigned a3 = *(const unsigned*)&xs[(wrow + g + 8) * XS_STRIDE + kb + 2 * tig + 8];
        #pragma unroll
        for (int nf = 0; nf < 8; ++nf) {
            unsigned b0 = *(const unsigned*)&wt[(nf * 8 + g) * XS_STRIDE + kb + 2 * tig];
            unsigned b1 = *(const unsigned*)&wt[(nf * 8 + g) * XS_STRIDE + kb + 2 * tig + 8];
            mma16816(d[nf][0], d[nf][1], d[nf][2], d[nf][3],
                     a0, a1, a2, a3, b0, b1);
        }
    }

    float be[4][2];
    #pragma unroll
    for (int nf = 4; nf < 8; ++nf) {
        int oc = nf * 8 + 2 * tig - 32;
        be[nf - 4][0] = __ldg(&beye[oc]);
        be[nf - 4][1] = __ldg(&beye[oc + 1]);
    }

    __syncthreads();   // done reading xs/wt; reuse smem for output staging

    __half* slin = (__half*)sm;                        // [32][SL_STRIDE] halves
    float*  seye = (float*)(sm + 32 * SL_STRIDE * 2);  // [128][SE_STRIDE] floats

    const int b        = warp >> 1;            // batch this warp owns
    const int nodeBase = (warp & 1) * 16;

    #pragma unroll
    for (int h2 = 0; h2 < 2; ++h2) {
        int node = nodeBase + g + 8 * h2;
        int r    = wrow + g + 8 * h2;          // tile row = 32*b + node
        #pragma unroll
        for (int nf = 0; nf < 4; ++nf) {
            int ch = nf * 8 + 2 * tig;
            float v0 = h2 ? d[nf][2] : d[nf][0];
            float v1 = h2 ? d[nf][3] : d[nf][1];
            slin[node * SL_STRIDE + ch * 4 + b]       = __float2half_rn(v0);
            slin[node * SL_STRIDE + (ch + 1) * 4 + b] = __float2half_rn(v1);
        }
        #pragma unroll
        for (int nf = 4; nf < 8; ++nf) {
            int c = (nf - 4) * 8 + 2 * tig;
            float v0 = (h2 ? d[nf][2] : d[nf][0]) + be[nf - 4][0];
            float v1 = (h2 ? d[nf][3] : d[nf][1]) + be[nf - 4][1];
            seye[r * SE_STRIDE + c]     = v0;
            seye[r * SE_STRIDE + c + 1] = v1;
        }
    }
    __syncthreads();

    #pragma unroll
    for (int it = 0; it < 4; ++it) {
        int idx  = tid + it * 256;             // 0..1023
        int node = idx >> 5;
        int q    = idx & 31;
        int n    = node0 + node;
        if (n < NN) {
            uint2 v = *(const uint2*)&slin[node * SL_STRIDE + q * 4];
            *(uint2*)&g_hlin[(size_t)n * 128 + q * 4] = v;   // re-read by gather: keep
        }
    }
    #pragma unroll
    for (int it = 0; it < 8; ++it) {
        int idx = tid + it * 256;              // 0..2047
        int row = idx >> 4;
        int q   = idx & 15;
        int bb  = row >> 5;
        int node = row & 31;
        int n   = node0 + node;
        if (n < NN) {
            float2 v = *(const float2*)&seye[row * SE_STRIDE + q * 2];
            __stcs((float2*)&out[((size_t)bb * NN + n) * 64 + 32 + q * 2], v);
        }
    }
}

// ---------------- gather: one warp per node, 64-thread blocks, PDL -----------
__global__ __launch_bounds__(GATHER_TPB) void gather_kernel(const float* __restrict__ blin,
                                                            float* __restrict__ out) {
    int n    = (blockIdx.x * GATHER_TPB + threadIdx.x) >> 5;
    int lane = threadIdx.x & 31;

    float bl = blin[lane];                 // pre-sync prefetch

    cudaGridDependencySynchronize();

    // reset phase flags for the next invocation (K1 fully complete here)
    if (blockIdx.x == 0 && threadIdx.x == 0) {
        g_hist_done = 0;
        g_scan_done = 0;
    }

    int s = g_offsets[n];
    int t = g_offsets[n + 1];

    float a0 = 0.f, a1 = 0.f, a2 = 0.f, a3 = 0.f;
    int e = s;

    // alignment prologue: make e even so int2 pairs are 16B-aligned
    if ((e & 1) && e < t) {
        int2 p = g_csr[e];
        uint2 q = *(const uint2*)(g_hlin + (size_t)p.x * 128 + lane * 4);
        float sv = __int_as_float(p.y);
        float2 u01 = __half22float2(*(__half2*)&q.x);
        float2 u23 = __half22float2(*(__half2*)&q.y);
        a0 += sv * u01.x; a1 += sv * u01.y; a2 += sv * u23.x; a3 += sv * u23.y;
        ++e;
    }

    for (; e + 4 <= t; e += 4) {
        uint4 pa = *(const uint4*)&g_csr[e];       // edges e, e+1
        uint4 pb = *(const uint4*)&g_csr[e + 2];   // edges e+2, e+3
        uint2 q0 = *(const uint2*)(g_hlin + (size_t)pa.x * 128 + lane * 4);
        uint2 q1 = *(const uint2*)(g_hlin + (size_t)pa.z * 128 + lane * 4);
        uint2 q2 = *(const uint2*)(g_hlin + (size_t)pb.x * 128 + lane * 4);
        uint2 q3 = *(const uint2*)(g_hlin + (size_t)pb.z * 128 + lane * 4);
        float s0 = __uint_as_float(pa.y), s1 = __uint_as_float(pa.w);
        float s2 = __uint_as_float(pb.y), s3 = __uint_as_float(pb.w);
        float2 u01, u23;
        u01 = __half22float2(*(__half2*)&q0.x); u23 = __half22float2(*(__half2*)&q0.y);
        a0 += s0 * u01.x; a1 += s0 * u01.y; a2 += s0 * u23.x; a3 += s0 * u23.y;
        u01 = __half22float2(*(__half2*)&q1.x); u23 = __half22float2(*(__half2*)&q1.y);
        a0 += s1 * u01.x; a1 += s1 * u01.y; a2 += s1 * u23.x; a3 += s1 * u23.y;
        u01 = __half22float2(*(__half2*)&q2.x); u23 = __half22float2(*(__half2*)&q2.y);
        a0 += s2 * u01.x; a1 += s2 * u01.y; a2 += s2 * u23.x; a3 += s2 * u23.y;
        u01 = __half22float2(*(__half2*)&q3.x); u23 = __half22float2(*(__half2*)&q3.y);
        a0 += s3 * u01.x; a1 += s3 * u01.y; a2 += s3 * u23.x; a3 += s3 * u23.y;
    }
    if (e + 2 <= t) {
        uint4 pa = *(const uint4*)&g_csr[e];
        uint2 q0 = *(const uint2*)(g_hlin + (size_t)pa.x * 128 + lane * 4);
        uint2 q1 = *(const uint2*)(g_hlin + (size_t)pa.z * 128 + lane * 4);
        float s0 = __uint_as_float(pa.y), s1 = __uint_as_float(pa.w);
        float2 u01, u23;
        u01 = __half22float2(*(__half2*)&q0.x); u23 = __half22float2(*(__half2*)&q0.y);
        a0 += s0 * u01.x; a1 += s0 * u01.y; a2 += s0 * u23.x; a3 += s0 * u23.y;
        u01 = __half22float2(*(__half2*)&q1.x); u23 = __half22float2(*(__half2*)&q1.y);
        a0 += s1 * u01.x; a1 += s1 * u01.y; a2 += s1 * u23.x; a3 += s1 * u23.y;
        e += 2;
    }
    if (e < t) {
        int2 p = g_csr[e];
        uint2 q = *(const uint2*)(g_hlin + (size_t)p.x * 128 + lane * 4);
        float sv = __int_as_float(p.y);
        float2 u01 = __half22float2(*(__half2*)&q.x);
        float2 u23 = __half22float2(*(__half2*)&q.y);
        a0 += sv * u01.x; a1 += sv * u01.y; a2 += sv * u23.x; a3 += sv * u23.y;
    }

    out[((size_t)0 * NN + n) * 64 + lane] = a0 + bl;
    out[((size_t)1 * NN + n) * 64 + lane] = a1 + bl;
    out[((size_t)2 * NN + n) * 64 + lane] = a2 + bl;
    out[((size_t)3 * NN + n) * 64 + lane] = a3 + bl;
}

// ---------------- launch: K1 (flag-chained) + PDL gather ---------------------
extern "C" void kernel_launch(void* const* d_in, const int* in_sizes, int n_in,
                              void* d_out, int out_size) {
    const float* x    = (const float*)d_in[0];
    const float* vals = (const float*)d_in[1];
    const float* Wlin = (const float*)d_in[2];
    const float* blin = (const float*)d_in[3];
    const float* Weye = (const float*)d_in[4];
    const float* beye = (const float*)d_in[5];
    const int*   rows = (const int*)d_in[6];
    const int*   cols = (const int*)d_in[7];
    float* out = (float*)d_out;
    (void)in_sizes; (void)n_in; (void)out_size;

    // g_counts / g_blocksums / flags are zero on entry (zero-init at load;
    // scanB / scatter / gather re-zero them each call).
    k1_fused_kernel<<<K1_GRID, 256>>>(rows, cols, vals, x, Wlin, Weye, beye, out);

    cudaLaunchConfig_t cfg = {};
    cfg.gridDim = dim3(GATHER_BLOCKS);
    cfg.blockDim = dim3(GATHER_TPB);
    cudaLaunchAttribute attr[1];
    attr[0].id = cudaLaunchAttributeProgrammaticStreamSerialization;
    attr[0].val.programmaticStreamSerializationAllowed = 1;
    cfg.attrs = attr;
    cfg.numAttrs = 1;
    cudaLaunchKernelEx(&cfg, gather_kernel, blin, out);
}